// round 16
// baseline (speedup 1.0000x reference)
#include <cuda_runtime.h>
#include <cuda_fp16.h>
#include <math.h>
#include <cstdint>

#define S_DIM 128
#define R_DIM 256
#define CS 256
#define CH 32
#define CZ 128
#define MDIM 8192           // R_DIM * CH
#define LN_EPS 1e-5f
#define MASK_EPS 1e-3f

// Scratch (static __device__ arrays — no cudaMalloc allowed)
__device__ __half g_a[MDIM * S_DIM];                // A fp16, K-major [m][s], 2 MB
__device__ __half g_b[MDIM * S_DIM];                // B fp16
__device__ __half g_o[(size_t)65536 * 1024];        // outer fp16 [p][hk], 134 MB
__device__ __half g_w[CZ * 1024];                   // w_out^T fp16 [z][k]
__device__ __half g_wp[64 * CS];                    // [w1|w2]^T fp16 [n=64][c=256]

// ---------------- helpers ---------------------------------------------------
__device__ __forceinline__ void mma_f16(float* c, const uint32_t* a, const uint32_t* b) {
    asm volatile(
        "mma.sync.aligned.m16n8k16.row.col.f32.f16.f16.f32 "
        "{%0,%1,%2,%3},{%4,%5,%6,%7},{%8,%9},{%0,%1,%2,%3};"
        : "+f"(c[0]), "+f"(c[1]), "+f"(c[2]), "+f"(c[3])
        : "r"(a[0]), "r"(a[1]), "r"(a[2]), "r"(a[3]), "r"(b[0]), "r"(b[1]));
}
__device__ __forceinline__ void ldsm_x4(uint32_t* r, uint32_t addr) {
    asm volatile("ldmatrix.sync.aligned.m8n8.x4.shared.b16 {%0,%1,%2,%3}, [%4];"
        : "=r"(r[0]), "=r"(r[1]), "=r"(r[2]), "=r"(r[3]) : "r"(addr));
}
__device__ __forceinline__ uint32_t pack_h2(float x, float y) {
    unsigned lx = __half_as_ushort(__float2half_rn(x));
    unsigned ly = __half_as_ushort(__float2half_rn(y));
    return lx | (ly << 16);
}
__device__ __forceinline__ uint32_t smem_u32(const void* p) {
    uint32_t a;
    asm("{ .reg .u64 t; cvta.to.shared.u64 t, %1; cvt.u32.u64 %0, t; }"
        : "=r"(a) : "l"(p));
    return a;
}
__device__ __forceinline__ void cp16(uint32_t dst, const void* src) {
    asm volatile("cp.async.cg.shared.global [%0], [%1], 16;" :: "r"(dst), "l"(src));
}
#define CP_COMMIT() asm volatile("cp.async.commit_group;" ::: "memory")
#define CP_WAIT1()  asm volatile("cp.async.wait_group 1;" ::: "memory")
#define CP_WAIT0()  asm volatile("cp.async.wait_group 0;" ::: "memory")

// ---------------- gemm1 single-shot: block 128m x 256n, K=128 ---------------
#define G1_ROW_B 272                  // 256B data + 16B pad per row
#define G1_OFF_B (128 * G1_ROW_B)     // A = 128 rows
#define SMEM_G1  (G1_OFF_B + 256 * G1_ROW_B)  // + B 256 rows = 104448 B
#define CS1_STRIDE_U32 132            // C repack row: 256 fp16 + 16B pad

// ---------------- gemm2: block 256p x 128z, K-chunk 64, 3 stages ------------
#define R2_ROW_B 144                  // 128B data + 16B pad
#define OFF2_A   0
#define OFF2_B   (256 * R2_ROW_B)     // A = 256 rows = 36864
#define ST2_B    (OFF2_B + 128 * R2_ROW_B)    // + B 128 rows = 55296 per stage
#define NST2     3
#define SMEM_G2  (NST2 * ST2_B)       // 165888 B

// ---------------- fused proj: A 128x256 fp16 + B 64x256 fp16 ---------------
#define P_ROW_B  528                  // 512B data + 16B pad
#define P_OFF_B  (128 * P_ROW_B)      // 67584
#define SMEM_P   (P_OFF_B + 64 * P_ROW_B)   // 101376 B
#define CS_STRIDE_U16 136             // Cs2 row = 272 B (128 fp16 + 16B pad)

// ---------------------------------------------------------------------------
// Kernel 0a: transpose+convert w_out [k][z] fp32 -> g_w [z][k] fp16
// ---------------------------------------------------------------------------
__global__ void k_wprep(const float* __restrict__ w_out)
{
    __shared__ float t[32][33];
    int tx = threadIdx.x, ty = threadIdx.y;
    int k0 = blockIdx.x * 32, z0 = blockIdx.y * 32;
    t[ty][tx] = w_out[(size_t)(k0 + ty) * CZ + z0 + tx];
    __syncthreads();
    g_w[(size_t)(z0 + ty) * 1024 + k0 + tx] = __float2half_rn(t[tx][ty]);
}

// ---------------------------------------------------------------------------
// Kernel 0b: pack [w1|w2]^T fp16 -> g_wp[n][c]
// ---------------------------------------------------------------------------
__global__ void k_w12prep(const float* __restrict__ w1, const float* __restrict__ w2)
{
    int n = blockIdx.x;        // 0..63
    int c = threadIdx.x;       // 0..255
    float v = (n < 32) ? w1[c * CH + n] : w2[c * CH + (n - 32)];
    g_wp[n * CS + c] = __float2half_rn(v);
}

// ---------------------------------------------------------------------------
// Kernel 1: FUSED LayerNorm + projection via HMMA (unchanged R15).
// ---------------------------------------------------------------------------
__global__ __launch_bounds__(256, 2) void k_proj_fused(
    const float* __restrict__ m, const float* __restrict__ mask,
    const float* __restrict__ lnw, const float* __restrict__ lnb,
    const float* __restrict__ b1, const float* __restrict__ b2)
{
    extern __shared__ char smem[];
    __shared__ float lnws[CS], lnbs[CS];
    __shared__ float masks[128];
    uint32_t sb = smem_u32(smem);

    int tid = threadIdx.x, lane = tid & 31, warp = tid >> 5;
    int g = lane >> 2, tg = lane & 3;
    int r = blockIdx.x;

    lnws[tid] = lnw[tid];
    lnbs[tid] = lnb[tid];
    if (tid < 128) masks[tid] = mask[tid * R_DIM + r];

    const uint4* pwp = (const uint4*)g_wp;
    #pragma unroll
    for (int u = 0; u < 8; u++) {
        int f = tid + u * 256;
        int row = f >> 5, q = f & 31;
        cp16(sb + P_OFF_B + row * P_ROW_B + q * 16, pwp + row * 32 + q);
    }
    CP_COMMIT();

    __syncthreads();   // lnws/lnbs/masks visible to all threads

    #pragma unroll 1
    for (int i = 0; i < 16; i++) {
        int s = warp * 16 + i;
        const float4* mrow = (const float4*)(m + ((size_t)s * R_DIM + r) * CS);
        float4 v0 = mrow[lane * 2];
        float4 v1 = mrow[lane * 2 + 1];
        float s1 = v0.x + v0.y + v0.z + v0.w + v1.x + v1.y + v1.z + v1.w;
        float s2 = v0.x*v0.x + v0.y*v0.y + v0.z*v0.z + v0.w*v0.w
                 + v1.x*v1.x + v1.y*v1.y + v1.z*v1.z + v1.w*v1.w;
        #pragma unroll
        for (int off = 16; off; off >>= 1) {
            s1 += __shfl_xor_sync(0xffffffffu, s1, off);
            s2 += __shfl_xor_sync(0xffffffffu, s2, off);
        }
        float mu   = s1 * (1.0f / CS);
        float var  = s2 * (1.0f / CS) - mu * mu;
        float rstd = rsqrtf(var + LN_EPS);
        int c0 = lane * 8;
        float t[8] = {v0.x, v0.y, v0.z, v0.w, v1.x, v1.y, v1.z, v1.w};
        float nv[8];
        #pragma unroll
        for (int q = 0; q < 8; q++)
            nv[q] = (t[q] - mu) * rstd * lnws[c0 + q] + lnbs[c0 + q];
        uint4 pk = make_uint4(pack_h2(nv[0], nv[1]), pack_h2(nv[2], nv[3]),
                              pack_h2(nv[4], nv[5]), pack_h2(nv[6], nv[7]));
        *(uint4*)(smem + s * P_ROW_B + lane * 16) = pk;
    }
    CP_WAIT0();
    __syncthreads();

    int wm = warp & 3, wn = warp >> 2;
    uint32_t rsel = (uint32_t)(lane & 15) * P_ROW_B + (uint32_t)(lane >> 4) * 16;
    uint32_t aB0 = sb + (uint32_t)(wm * 32) * P_ROW_B + rsel;
    uint32_t aB1 = aB0 + 16 * P_ROW_B;
    uint32_t bB0 = sb + P_OFF_B + (uint32_t)(wn * 32) * P_ROW_B + rsel;
    uint32_t bB1 = bB0 + 16 * P_ROW_B;

    float acc[2][4][4];
    #pragma unroll
    for (int a = 0; a < 2; a++)
        #pragma unroll
        for (int b = 0; b < 4; b++)
            #pragma unroll
            for (int c = 0; c < 4; c++) acc[a][b][c] = 0.f;

    #pragma unroll
    for (int ks = 0; ks < 16; ks++) {
        uint32_t ko = ks * 32;
        uint32_t ah[2][4], bm[2][4];
        ldsm_x4(ah[0], aB0 + ko);
        ldsm_x4(ah[1], aB1 + ko);
        ldsm_x4(bm[0], bB0 + ko);
        ldsm_x4(bm[1], bB1 + ko);
        #pragma unroll
        for (int mt = 0; mt < 2; mt++)
            #pragma unroll
            for (int nt = 0; nt < 4; nt++) {
                uint32_t b2[2] = { bm[nt >> 1][nt & 1], bm[nt >> 1][2 + (nt & 1)] };
                mma_f16(acc[mt][nt], ah[mt], b2);
            }
    }
    __syncthreads();

    unsigned short* cs = (unsigned short*)(smem + P_OFF_B);
    #pragma unroll
    for (int mt = 0; mt < 2; mt++) {
        #pragma unroll
        for (int hf = 0; hf < 2; hf++) {
            int s = wm * 32 + mt * 16 + g + hf * 8;
            float mk = masks[s];
            #pragma unroll
            for (int nt = 0; nt < 4; nt++) {
                int n0 = wn * 32 + nt * 8 + 2 * tg;
                const float* bb = (n0 < 32) ? (b1 + n0) : (b2 + (n0 - 32));
                float vx = (acc[mt][nt][hf * 2 + 0] + bb[0]) * mk;
                float vy = (acc[mt][nt][hf * 2 + 1] + bb[1]) * mk;
                cs[n0 * CS_STRIDE_U16 + s]       = __half_as_ushort(__float2half_rn(vx));
                cs[(n0 + 1) * CS_STRIDE_U16 + s] = __half_as_ushort(__float2half_rn(vy));
            }
        }
    }
    __syncthreads();

    #pragma unroll
    for (int u = 0; u < 4; u++) {
        int f = tid + u * 256;
        int n = f >> 4, q = f & 15;
        uint4 v = *(const uint4*)(cs + n * CS_STRIDE_U16 + q * 8);
        __half* dst = (n < 32) ? g_a : g_b;
        int h = n & 31;
        ((uint4*)dst)[(size_t)(r * CH + h) * 16 + q] = v;
    }
}

// ---------------------------------------------------------------------------
// Kernel 2: outer contraction, single-shot K=128 fp16 HMMA.
// Block 128m x 256n, 16 warps (4m x 4n), warp tile 32x64 (192 B/HMMA L1).
// ---------------------------------------------------------------------------
__global__ __launch_bounds__(512, 1) void k_gemm1_mma()
{
    extern __shared__ char smem[];
    uint32_t sb = smem_u32(smem);

    int tid = threadIdx.x, lane = tid & 31, warp = tid >> 5;
    int g = lane >> 2, tg = lane & 3;
    int wm = warp & 3, wn = warp >> 2;      // 4m x 4n warps
    int m0 = blockIdx.x * 128, n0 = blockIdx.y * 256;
    int ib = m0 >> 5, jb = n0 >> 5;

    const uint4* pa = (const uint4*)g_a;   // row = 16 uint4 (128 s fp16)
    const uint4* pb = (const uint4*)g_b;

    // Load A (128 rows) + B (256 rows): 2048 + 4096 cp16
    #pragma unroll
    for (int u = 0; u < 4; u++) {
        int f = tid + u * 512;             // 0..2047
        int row = f >> 4, q = f & 15;
        cp16(sb + row * G1_ROW_B + q * 16, pa + (size_t)(m0 + row) * 16 + q);
    }
    #pragma unroll
    for (int u = 0; u < 8; u++) {
        int f = tid + u * 512;             // 0..4095
        int row = f >> 4, q = f & 15;
        cp16(sb + G1_OFF_B + row * G1_ROW_B + q * 16, pb + (size_t)(n0 + row) * 16 + q);
    }
    CP_COMMIT();
    CP_WAIT0();
    __syncthreads();

    uint32_t rsel = (uint32_t)(lane & 15) * G1_ROW_B + (uint32_t)(lane >> 4) * 16;
    uint32_t aB0 = sb + (uint32_t)(wm * 32 +  0) * G1_ROW_B + rsel;
    uint32_t aB1 = sb + (uint32_t)(wm * 32 + 16) * G1_ROW_B + rsel;
    uint32_t bB[4];
    #pragma unroll
    for (int ntp = 0; ntp < 4; ntp++)
        bB[ntp] = sb + G1_OFF_B + (uint32_t)(wn * 64 + ntp * 16) * G1_ROW_B + rsel;

    float acc[2][8][4];
    #pragma unroll
    for (int a = 0; a < 2; a++)
        #pragma unroll
        for (int b = 0; b < 8; b++)
            #pragma unroll
            for (int c = 0; c < 4; c++) acc[a][b][c] = 0.f;

    #pragma unroll
    for (int ks = 0; ks < 8; ks++) {
        uint32_t ko = ks * 32;
        uint32_t ah[2][4], bm[4][4];
        ldsm_x4(ah[0], aB0 + ko);
        ldsm_x4(ah[1], aB1 + ko);
        #pragma unroll
        for (int ntp = 0; ntp < 4; ntp++)
            ldsm_x4(bm[ntp], bB[ntp] + ko);
        #pragma unroll
        for (int mt = 0; mt < 2; mt++)
            #pragma unroll
            for (int nt = 0; nt < 8; nt++) {
                uint32_t b2[2] = { bm[nt >> 1][nt & 1], bm[nt >> 1][2 + (nt & 1)] };
                mma_f16(acc[mt][nt], ah[mt], b2);
            }
    }
    __syncthreads();   // done with operand smem; reuse for C repack

    // Repack C (fp16): Cs[m row][n col], row stride CS1_STRIDE_U32 u32
    uint32_t* Cs = (uint32_t*)smem;
    #pragma unroll
    for (int mt = 0; mt < 2; mt++) {
        #pragma unroll
        for (int hf = 0; hf < 2; hf++) {
            int mloc = wm * 32 + mt * 16 + g + hf * 8;
            #pragma unroll
            for (int nt = 0; nt < 8; nt++) {
                int nloc = wn * 64 + nt * 8 + 2 * tg;
                Cs[mloc * CS1_STRIDE_U32 + (nloc >> 1)] =
                    pack_h2(acc[mt][nt][hf * 2 + 0], acc[mt][nt][hf * 2 + 1]);
            }
        }
    }
    __syncthreads();

    // Coalesced store: 128 rows x 32 uint4 = 4096 uint4, 8 per thread
    uint4* o4 = (uint4*)g_o;
    #pragma unroll
    for (int u = 0; u < 8; u++) {
        int f = tid + u * 512;
        int row = f >> 5, q = f & 31;
        int i = ib + (row >> 5), h = row & 31;
        int j = jb + (q >> 2);
        uint4 v = *(const uint4*)&Cs[row * CS1_STRIDE_U32 + q * 4];
        o4[(size_t)(i * R_DIM + j) * 128 + h * 4 + (q & 3)] = v;
    }
}

// ---------------------------------------------------------------------------
// Kernel 3: output GEMM fp16 HMMA + bias + mask-norm.
// Block 256p x 128z (one full i-row), 16 warps (8m x 2n), warp 32x64,
// K-chunk 64, 3 stages.
// ---------------------------------------------------------------------------
__global__ __launch_bounds__(512, 1) void k_gemm2_mma(
    const float* __restrict__ mask, const float* __restrict__ b_out,
    float* __restrict__ out)
{
    extern __shared__ char smem[];
    __shared__ float norms[256];
    uint32_t sb = smem_u32(smem);

    int tid = threadIdx.x, lane = tid & 31, warp = tid >> 5;
    int g = lane >> 2, tg = lane & 3;
    int wm = warp & 7, wn = warp >> 3;     // 8m x 2n warps
    int p0 = blockIdx.x * 256;
    int i  = blockIdx.x;                   // pairs (i, j=0..255)

    if (tid < 256) {
        float nacc = 0.f;
        #pragma unroll 4
        for (int s = 0; s < S_DIM; s++)
            nacc += mask[s * R_DIM + i] * mask[s * R_DIM + tid];
        norms[tid] = nacc;
    }

    const uint4* pa = (const uint4*)g_o;   // row = 128 uint4 (1024 fp16)
    const uint4* pb = (const uint4*)g_w;

    float acc[2][8][4];
    #pragma unroll
    for (int a = 0; a < 2; a++)
        #pragma unroll
        for (int b = 0; b < 8; b++)
            #pragma unroll
            for (int c = 0; c < 4; c++) acc[a][b][c] = 0.f;

    uint32_t rsel = (uint32_t)(lane & 15) * R2_ROW_B + (uint32_t)(lane >> 4) * 16;
    uint32_t aO0 = OFF2_A + (uint32_t)(wm * 32 +  0) * R2_ROW_B + rsel;
    uint32_t aO1 = OFF2_A + (uint32_t)(wm * 32 + 16) * R2_ROW_B + rsel;
    uint32_t bO[4];
    #pragma unroll
    for (int ntp = 0; ntp < 4; ntp++)
        bO[ntp] = OFF2_B + (uint32_t)(wn * 64 + ntp * 16) * R2_ROW_B + rsel;

    // per-chunk copy indices: A 2048 cp16 (4/thr), B 1024 cp16 (2/thr)
    // prologue: chunks 0,1 into stages 0,1
    #pragma unroll
    for (int pc = 0; pc < NST2 - 1; pc++) {
        uint32_t st = sb + pc * ST2_B;
        #pragma unroll
        for (int u = 0; u < 4; u++) {
            int f = tid + u * 512;
            int row = f >> 3, q = f & 7;
            cp16(st + OFF2_A + row * R2_ROW_B + q * 16,
                 pa + (size_t)(p0 + row) * 128 + pc * 8 + q);
        }
        #pragma unroll
        for (int u = 0; u < 2; u++) {
            int f = tid + u * 512;
            int row = f >> 3, q = f & 7;
            cp16(st + OFF2_B + row * R2_ROW_B + q * 16,
                 pb + (size_t)row * 128 + pc * 8 + q);
        }
        CP_COMMIT();
    }

    for (int kc = 0; kc < 16; kc++) {
        CP_WAIT1();
        __syncthreads();
        int kp = kc + NST2 - 1;
        if (kp < 16) {
            uint32_t st = sb + (kp % NST2) * ST2_B;
            #pragma unroll
            for (int u = 0; u < 4; u++) {
                int f = tid + u * 512;
                int row = f >> 3, q = f & 7;
                cp16(st + OFF2_A + row * R2_ROW_B + q * 16,
                     pa + (size_t)(p0 + row) * 128 + kp * 8 + q);
            }
            #pragma unroll
            for (int u = 0; u < 2; u++) {
                int f = tid + u * 512;
                int row = f >> 3, q = f & 7;
                cp16(st + OFF2_B + row * R2_ROW_B + q * 16,
                     pb + (size_t)row * 128 + kp * 8 + q);
            }
        }
        CP_COMMIT();

        uint32_t stage = sb + (kc % NST2) * ST2_B;
        #pragma unroll
        for (int ks = 0; ks < 4; ks++) {
            uint32_t ko = stage + ks * 32;
            uint32_t ah[2][4], bm[4][4];
            ldsm_x4(ah[0], aO0 + ko);
            ldsm_x4(ah[1], aO1 + ko);
            #pragma unroll
            for (int ntp = 0; ntp < 4; ntp++)
                ldsm_x4(bm[ntp], bO[ntp] + ko);
            #pragma unroll
            for (int mt = 0; mt < 2; mt++)
                #pragma unroll
                for (int nt = 0; nt < 8; nt++) {
                    uint32_t b2[2] = { bm[nt >> 1][nt & 1], bm[nt >> 1][2 + (nt & 1)] };
                    mma_f16(acc[mt][nt], ah[mt], b2);
                }
        }
    }

    // Epilogue: bias + norm divide, fp32 out
    #pragma unroll
    for (int mt = 0; mt < 2; mt++) {
        int pl = wm * 32 + mt * 16 + g;
        #pragma unroll
        for (int nt = 0; nt < 8; nt++) {
            int z = wn * 64 + nt * 8 + 2 * tg;
            float2 bz = *(const float2*)&b_out[z];
            #pragma unroll
            for (int hf = 0; hf < 2; hf++) {
                int pp = pl + hf * 8;
                float inv = 1.0f / (MASK_EPS + norms[pp]);
                float cx = (acc[mt][nt][hf * 2 + 0] + bz.x) * inv;
                float cy = (acc[mt][nt][hf * 2 + 1] + bz.y) * inv;
                *(float2*)&out[(size_t)(p0 + pp) * CZ + z] = make_float2(cx, cy);
            }
        }
    }
}

// ---------------------------------------------------------------------------
extern "C" void kernel_launch(void* const* d_in, const int* in_sizes, int n_in,
                              void* d_out, int out_size)
{
    const float* m     = (const float*)d_in[0];
    const float* mask  = (const float*)d_in[1];
    const float* lnw   = (const float*)d_in[2];
    const float* lnb   = (const float*)d_in[3];
    const float* w1    = (const float*)d_in[4];
    const float* b1    = (const float*)d_in[5];
    const float* w2    = (const float*)d_in[6];
    const float* b2    = (const float*)d_in[7];
    const float* w_out = (const float*)d_in[8];
    const float* b_out = (const float*)d_in[9];
    float* out = (float*)d_out;

    static int attr_done = 0;
    if (!attr_done) {
        cudaFuncSetAttribute(k_proj_fused,
            cudaFuncAttributeMaxDynamicSharedMemorySize, SMEM_P);
        cudaFuncSetAttribute(k_gemm1_mma,
            cudaFuncAttributeMaxDynamicSharedMemorySize, SMEM_G1);
        cudaFuncSetAttribute(k_gemm2_mma,
            cudaFuncAttributeMaxDynamicSharedMemorySize, SMEM_G2);
        attr_done = 1;
    }

    k_wprep<<<dim3(32, 4), dim3(32, 32)>>>(w_out);
    k_w12prep<<<64, 256>>>(w1, w2);
    k_proj_fused<<<256, 256, SMEM_P>>>(m, mask, lnw, lnb, b1, b2);
    k_gemm1_mma<<<dim3(64, 32), 512, SMEM_G1>>>();
    k_gemm2_mma<<<256, 512, SMEM_G2>>>(mask, b_out, out);
}

// round 17
// speedup vs baseline: 1.1628x; 1.1628x over previous
#include <cuda_runtime.h>
#include <cuda_fp16.h>
#include <math.h>
#include <cstdint>

#define S_DIM 128
#define R_DIM 256
#define CS 256
#define CH 32
#define CZ 128
#define MDIM 8192           // R_DIM * CH
#define LN_EPS 1e-5f
#define MASK_EPS 1e-3f

// Scratch (static __device__ arrays — no cudaMalloc allowed)
__device__ __half g_a[MDIM * S_DIM];                // A fp16, K-major [m][s], 2 MB
__device__ __half g_b[MDIM * S_DIM];                // B fp16
__device__ __half g_o[(size_t)65536 * 1024];        // outer fp16 [p][hk], 134 MB
__device__ __half g_w[CZ * 1024];                   // w_out^T fp16 [z][k]
__device__ __half g_wp[64 * CS];                    // [w1|w2]^T fp16 [n=64][c=256]

// ---------------- helpers ---------------------------------------------------
__device__ __forceinline__ void mma_f16(float* c, const uint32_t* a, const uint32_t* b) {
    asm volatile(
        "mma.sync.aligned.m16n8k16.row.col.f32.f16.f16.f32 "
        "{%0,%1,%2,%3},{%4,%5,%6,%7},{%8,%9},{%0,%1,%2,%3};"
        : "+f"(c[0]), "+f"(c[1]), "+f"(c[2]), "+f"(c[3])
        : "r"(a[0]), "r"(a[1]), "r"(a[2]), "r"(a[3]), "r"(b[0]), "r"(b[1]));
}
__device__ __forceinline__ void ldsm_x4(uint32_t* r, uint32_t addr) {
    asm volatile("ldmatrix.sync.aligned.m8n8.x4.shared.b16 {%0,%1,%2,%3}, [%4];"
        : "=r"(r[0]), "=r"(r[1]), "=r"(r[2]), "=r"(r[3]) : "r"(addr));
}
__device__ __forceinline__ uint32_t pack_h2(float x, float y) {
    unsigned lx = __half_as_ushort(__float2half_rn(x));
    unsigned ly = __half_as_ushort(__float2half_rn(y));
    return lx | (ly << 16);
}
__device__ __forceinline__ uint32_t smem_u32(const void* p) {
    uint32_t a;
    asm("{ .reg .u64 t; cvta.to.shared.u64 t, %1; cvt.u32.u64 %0, t; }"
        : "=r"(a) : "l"(p));
    return a;
}
__device__ __forceinline__ void cp16(uint32_t dst, const void* src) {
    asm volatile("cp.async.cg.shared.global [%0], [%1], 16;" :: "r"(dst), "l"(src));
}
#define CP_COMMIT() asm volatile("cp.async.commit_group;" ::: "memory")
#define CP_WAIT3()  asm volatile("cp.async.wait_group 3;" ::: "memory")
#define CP_WAIT0()  asm volatile("cp.async.wait_group 0;" ::: "memory")

// ---------------- gemm2 pipeline: K-chunk 32, 5 stages (R15) ----------------
#define RPAD 20               // u32 per row (64B data + 16B pad) -> conflict-free
#define ROW_B 80
#define ARR_B   (128 * ROW_B)         // 10240 B per array
#define ST_B    (ARR_B * 2)           // 20480 B per stage
#define OFF_A   0
#define OFF_B   ARR_B
#define NSTAGE  5
#define SMEM_G2 (NSTAGE * ST_B)       // 102400 B

// ---------------- gemm1 single-shot: K=128, one stage -----------------------
#define G1_RPAD  68                   // u32 per row (256B data + 16B pad)
#define G1_ROW_B 272
#define G1_OFF_B (128 * G1_ROW_B)     // 34816
#define SMEM_G1  (2 * 128 * G1_ROW_B) // 69632 B

// ---------------- fused proj: A 128x256 fp16 + B 64x256 fp16 ---------------
#define P_ROW_B  528                  // 512B data + 16B pad
#define P_OFF_B  (128 * P_ROW_B)      // 67584
#define SMEM_P   (P_OFF_B + 64 * P_ROW_B)   // 101376 B
#define CS_STRIDE_U16 136             // Cs2 row = 272 B (128 fp16 + 16B pad)

// ---------------------------------------------------------------------------
// Kernel 0a: transpose+convert w_out [k][z] fp32 -> g_w [z][k] fp16
// ---------------------------------------------------------------------------
__global__ void k_wprep(const float* __restrict__ w_out)
{
    __shared__ float t[32][33];
    int tx = threadIdx.x, ty = threadIdx.y;
    int k0 = blockIdx.x * 32, z0 = blockIdx.y * 32;
    t[ty][tx] = w_out[(size_t)(k0 + ty) * CZ + z0 + tx];
    __syncthreads();
    g_w[(size_t)(z0 + ty) * 1024 + k0 + tx] = __float2half_rn(t[tx][ty]);
}

// ---------------------------------------------------------------------------
// Kernel 0b: pack [w1|w2]^T fp16 -> g_wp[n][c]
// ---------------------------------------------------------------------------
__global__ void k_w12prep(const float* __restrict__ w1, const float* __restrict__ w2)
{
    int n = blockIdx.x;        // 0..63
    int c = threadIdx.x;       // 0..255
    float v = (n < 32) ? w1[c * CH + n] : w2[c * CH + (n - 32)];
    g_wp[n * CS + c] = __float2half_rn(v);
}

// ---------------------------------------------------------------------------
// Kernel 1: FUSED LayerNorm + projection via HMMA (unchanged R15).
// ---------------------------------------------------------------------------
__global__ __launch_bounds__(256, 2) void k_proj_fused(
    const float* __restrict__ m, const float* __restrict__ mask,
    const float* __restrict__ lnw, const float* __restrict__ lnb,
    const float* __restrict__ b1, const float* __restrict__ b2)
{
    extern __shared__ char smem[];
    __shared__ float lnws[CS], lnbs[CS];
    __shared__ float masks[128];
    uint32_t sb = smem_u32(smem);

    int tid = threadIdx.x, lane = tid & 31, warp = tid >> 5;
    int g = lane >> 2, tg = lane & 3;
    int r = blockIdx.x;

    lnws[tid] = lnw[tid];
    lnbs[tid] = lnb[tid];
    if (tid < 128) masks[tid] = mask[tid * R_DIM + r];

    const uint4* pwp = (const uint4*)g_wp;
    #pragma unroll
    for (int u = 0; u < 8; u++) {
        int f = tid + u * 256;
        int row = f >> 5, q = f & 31;
        cp16(sb + P_OFF_B + row * P_ROW_B + q * 16, pwp + row * 32 + q);
    }
    CP_COMMIT();

    __syncthreads();   // lnws/lnbs/masks visible to all threads

    #pragma unroll 1
    for (int i = 0; i < 16; i++) {
        int s = warp * 16 + i;
        const float4* mrow = (const float4*)(m + ((size_t)s * R_DIM + r) * CS);
        float4 v0 = mrow[lane * 2];
        float4 v1 = mrow[lane * 2 + 1];
        float s1 = v0.x + v0.y + v0.z + v0.w + v1.x + v1.y + v1.z + v1.w;
        float s2 = v0.x*v0.x + v0.y*v0.y + v0.z*v0.z + v0.w*v0.w
                 + v1.x*v1.x + v1.y*v1.y + v1.z*v1.z + v1.w*v1.w;
        #pragma unroll
        for (int off = 16; off; off >>= 1) {
            s1 += __shfl_xor_sync(0xffffffffu, s1, off);
            s2 += __shfl_xor_sync(0xffffffffu, s2, off);
        }
        float mu   = s1 * (1.0f / CS);
        float var  = s2 * (1.0f / CS) - mu * mu;
        float rstd = rsqrtf(var + LN_EPS);
        int c0 = lane * 8;
        float t[8] = {v0.x, v0.y, v0.z, v0.w, v1.x, v1.y, v1.z, v1.w};
        float nv[8];
        #pragma unroll
        for (int q = 0; q < 8; q++)
            nv[q] = (t[q] - mu) * rstd * lnws[c0 + q] + lnbs[c0 + q];
        uint4 pk = make_uint4(pack_h2(nv[0], nv[1]), pack_h2(nv[2], nv[3]),
                              pack_h2(nv[4], nv[5]), pack_h2(nv[6], nv[7]));
        *(uint4*)(smem + s * P_ROW_B + lane * 16) = pk;
    }
    CP_WAIT0();
    __syncthreads();

    int wm = warp & 3, wn = warp >> 2;
    uint32_t rsel = (uint32_t)(lane & 15) * P_ROW_B + (uint32_t)(lane >> 4) * 16;
    uint32_t aB0 = sb + (uint32_t)(wm * 32) * P_ROW_B + rsel;
    uint32_t aB1 = aB0 + 16 * P_ROW_B;
    uint32_t bB0 = sb + P_OFF_B + (uint32_t)(wn * 32) * P_ROW_B + rsel;
    uint32_t bB1 = bB0 + 16 * P_ROW_B;

    float acc[2][4][4];
    #pragma unroll
    for (int a = 0; a < 2; a++)
        #pragma unroll
        for (int b = 0; b < 4; b++)
            #pragma unroll
            for (int c = 0; c < 4; c++) acc[a][b][c] = 0.f;

    #pragma unroll
    for (int ks = 0; ks < 16; ks++) {
        uint32_t ko = ks * 32;
        uint32_t ah[2][4], bm[2][4];
        ldsm_x4(ah[0], aB0 + ko);
        ldsm_x4(ah[1], aB1 + ko);
        ldsm_x4(bm[0], bB0 + ko);
        ldsm_x4(bm[1], bB1 + ko);
        #pragma unroll
        for (int mt = 0; mt < 2; mt++)
            #pragma unroll
            for (int nt = 0; nt < 4; nt++) {
                uint32_t b2[2] = { bm[nt >> 1][nt & 1], bm[nt >> 1][2 + (nt & 1)] };
                mma_f16(acc[mt][nt], ah[mt], b2);
            }
    }
    __syncthreads();

    unsigned short* cs = (unsigned short*)(smem + P_OFF_B);
    #pragma unroll
    for (int mt = 0; mt < 2; mt++) {
        #pragma unroll
        for (int hf = 0; hf < 2; hf++) {
            int s = wm * 32 + mt * 16 + g + hf * 8;
            float mk = masks[s];
            #pragma unroll
            for (int nt = 0; nt < 4; nt++) {
                int n0 = wn * 32 + nt * 8 + 2 * tg;
                const float* bb = (n0 < 32) ? (b1 + n0) : (b2 + (n0 - 32));
                float vx = (acc[mt][nt][hf * 2 + 0] + bb[0]) * mk;
                float vy = (acc[mt][nt][hf * 2 + 1] + bb[1]) * mk;
                cs[n0 * CS_STRIDE_U16 + s]       = __half_as_ushort(__float2half_rn(vx));
                cs[(n0 + 1) * CS_STRIDE_U16 + s] = __half_as_ushort(__float2half_rn(vy));
            }
        }
    }
    __syncthreads();

    #pragma unroll
    for (int u = 0; u < 4; u++) {
        int f = tid + u * 256;
        int n = f >> 4, q = f & 15;
        uint4 v = *(const uint4*)(cs + n * CS_STRIDE_U16 + q * 8);
        __half* dst = (n < 32) ? g_a : g_b;
        int h = n & 31;
        ((uint4*)dst)[(size_t)(r * CH + h) * 16 + q] = v;
    }
}

// ---------------------------------------------------------------------------
// Kernel 2: outer contraction, single-shot K=128 fp16 HMMA.
// 256 threads, 8 warps (4m x 2n), warp tile 32x64 — 2 CTAs/SM preserved.
// ---------------------------------------------------------------------------
__global__ __launch_bounds__(256, 2) void k_gemm1_mma()
{
    extern __shared__ char smem[];
    uint32_t sb = smem_u32(smem);

    int tid = threadIdx.x, lane = tid & 31, warp = tid >> 5;
    int g = lane >> 2, tg = lane & 3;
    int wm = warp & 3, wn = warp >> 2;      // 4m x 2n warps
    int m0 = blockIdx.x * 128, n0 = blockIdx.y * 128;
    int ib = m0 >> 5, jb = n0 >> 5;

    const uint4* pa = (const uint4*)g_a;   // row = 16 uint4 (128 s fp16)
    const uint4* pb = (const uint4*)g_b;

    // Load A + B tiles: 2048 cp16 each, 8 per thread
    #pragma unroll
    for (int u = 0; u < 8; u++) {
        int f = tid + u * 256;             // 0..2047
        int row = f >> 4, q = f & 15;
        cp16(sb + row * G1_ROW_B + q * 16,            pa + (size_t)(m0 + row) * 16 + q);
        cp16(sb + G1_OFF_B + row * G1_ROW_B + q * 16, pb + (size_t)(n0 + row) * 16 + q);
    }
    CP_COMMIT();
    CP_WAIT0();
    __syncthreads();

    uint32_t rsel = (uint32_t)(lane & 15) * G1_ROW_B + (uint32_t)(lane >> 4) * 16;
    uint32_t aB0 = sb + (uint32_t)(wm * 32 +  0) * G1_ROW_B + rsel;
    uint32_t aB1 = sb + (uint32_t)(wm * 32 + 16) * G1_ROW_B + rsel;
    uint32_t bB[4];
    #pragma unroll
    for (int ntp = 0; ntp < 4; ntp++)
        bB[ntp] = sb + G1_OFF_B + (uint32_t)(wn * 64 + ntp * 16) * G1_ROW_B + rsel;

    float acc[2][8][4];
    #pragma unroll
    for (int a = 0; a < 2; a++)
        #pragma unroll
        for (int b = 0; b < 8; b++)
            #pragma unroll
            for (int c = 0; c < 4; c++) acc[a][b][c] = 0.f;

    #pragma unroll
    for (int ks = 0; ks < 8; ks++) {
        uint32_t ko = ks * 32;
        uint32_t ah[2][4], bm[4][4];
        ldsm_x4(ah[0], aB0 + ko);
        ldsm_x4(ah[1], aB1 + ko);
        #pragma unroll
        for (int ntp = 0; ntp < 4; ntp++)
            ldsm_x4(bm[ntp], bB[ntp] + ko);
        #pragma unroll
        for (int mt = 0; mt < 2; mt++)
            #pragma unroll
            for (int nt = 0; nt < 8; nt++) {
                uint32_t b2[2] = { bm[nt >> 1][nt & 1], bm[nt >> 1][2 + (nt & 1)] };
                mma_f16(acc[mt][nt], ah[mt], b2);
            }
    }
    __syncthreads();   // done with operand smem; reuse for C repack

    // Repack C (fp16): Cs[m row][n col], row stride G1_RPAD u32
    uint32_t* Cs = (uint32_t*)smem;
    #pragma unroll
    for (int mt = 0; mt < 2; mt++) {
        #pragma unroll
        for (int hf = 0; hf < 2; hf++) {
            int mloc = wm * 32 + mt * 16 + g + hf * 8;
            #pragma unroll
            for (int nt = 0; nt < 8; nt++) {
                int nloc = wn * 64 + nt * 8 + 2 * tg;
                Cs[mloc * G1_RPAD + (nloc >> 1)] =
                    pack_h2(acc[mt][nt][hf * 2 + 0], acc[mt][nt][hf * 2 + 1]);
            }
        }
    }
    __syncthreads();

    // Coalesced store: 2048 uint4, 8 per thread
    uint4* o4 = (uint4*)g_o;
    #pragma unroll
    for (int u = 0; u < 8; u++) {
        int f = tid + u * 256;
        int row = f >> 4, q = f & 15;
        int i = ib + (row >> 5), h = row & 31;
        int j = jb + (q >> 2);
        uint4 v = *(const uint4*)&Cs[row * G1_RPAD + q * 4];
        o4[(size_t)(i * R_DIM + j) * 128 + h * 4 + (q & 3)] = v;
    }
}

// ---------------------------------------------------------------------------
// Kernel 3: output GEMM fp16 HMMA + bias + mask-norm (unchanged R15).
// ---------------------------------------------------------------------------
__global__ __launch_bounds__(512, 2) void k_gemm2_mma(
    const float* __restrict__ mask, const float* __restrict__ b_out,
    float* __restrict__ out)
{
    extern __shared__ char smem[];
    __shared__ float norms[128];
    uint32_t sb = smem_u32(smem);

    int tid = threadIdx.x, lane = tid & 31, warp = tid >> 5;
    int g = lane >> 2, tg = lane & 3;
    int wm = warp & 3, wn = warp >> 2;
    int p0 = blockIdx.x * 128;
    int i  = p0 >> 8;
    int j0 = p0 & 255;

    if (tid < 128) {
        float nacc = 0.f;
        #pragma unroll 4
        for (int s = 0; s < S_DIM; s++)
            nacc += mask[s * R_DIM + i] * mask[s * R_DIM + j0 + tid];
        norms[tid] = nacc;
    }

    const uint4* pa = (const uint4*)g_o;
    const uint4* pb = (const uint4*)g_w;

    float acc[2][4][4];
    #pragma unroll
    for (int a = 0; a < 2; a++)
        #pragma unroll
        for (int b = 0; b < 4; b++)
            #pragma unroll
            for (int c = 0; c < 4; c++) acc[a][b][c] = 0.f;

    uint32_t rsel = (uint32_t)(lane & 15) * ROW_B + (uint32_t)(lane >> 4) * 16;
    uint32_t aO0 = OFF_A + (uint32_t)(wm * 32 +  0) * ROW_B + rsel;
    uint32_t aO1 = OFF_A + (uint32_t)(wm * 32 + 16) * ROW_B + rsel;
    uint32_t bO0 = OFF_B + (uint32_t)(wn * 32 +  0) * ROW_B + rsel;
    uint32_t bO1 = OFF_B + (uint32_t)(wn * 32 + 16) * ROW_B + rsel;

    int rA = tid >> 2, qA = tid & 3;

    #pragma unroll
    for (int pc = 0; pc < NSTAGE - 1; pc++) {
        uint32_t st = sb + pc * ST_B;
        cp16(st + OFF_A + rA * ROW_B + qA * 16, pa + (size_t)(p0 + rA) * 128 + pc * 4 + qA);
        cp16(st + OFF_B + rA * ROW_B + qA * 16, pb + (size_t)rA * 128 + pc * 4 + qA);
        CP_COMMIT();
    }

    for (int kc = 0; kc < 32; kc++) {
        CP_WAIT3();
        __syncthreads();
        int kp = kc + NSTAGE - 1;
        if (kp < 32) {
            uint32_t st = sb + (kp % NSTAGE) * ST_B;
            cp16(st + OFF_A + rA * ROW_B + qA * 16, pa + (size_t)(p0 + rA) * 128 + kp * 4 + qA);
            cp16(st + OFF_B + rA * ROW_B + qA * 16, pb + (size_t)rA * 128 + kp * 4 + qA);
        }
        CP_COMMIT();

        uint32_t stage = sb + (kc % NSTAGE) * ST_B;
        #pragma unroll
        for (int ks = 0; ks < 2; ks++) {
            uint32_t ko = stage + ks * 32;
            uint32_t ah[2][4], bm[2][4];
            ldsm_x4(ah[0], aO0 + ko);
            ldsm_x4(ah[1], aO1 + ko);
            ldsm_x4(bm[0], bO0 + ko);
            ldsm_x4(bm[1], bO1 + ko);
            #pragma unroll
            for (int mt = 0; mt < 2; mt++)
                #pragma unroll
                for (int nt = 0; nt < 4; nt++) {
                    uint32_t b2[2] = { bm[nt >> 1][nt & 1], bm[nt >> 1][2 + (nt & 1)] };
                    mma_f16(acc[mt][nt], ah[mt], b2);
                }
        }
    }

    #pragma unroll
    for (int mt = 0; mt < 2; mt++) {
        int pl = wm * 32 + mt * 16 + g;
        #pragma unroll
        for (int nt = 0; nt < 4; nt++) {
            int z = wn * 32 + nt * 8 + 2 * tg;
            float2 bz = *(const float2*)&b_out[z];
            #pragma unroll
            for (int hf = 0; hf < 2; hf++) {
                int pp = pl + hf * 8;
                float inv = 1.0f / (MASK_EPS + norms[pp]);
                float cx = (acc[mt][nt][hf * 2 + 0] + bz.x) * inv;
                float cy = (acc[mt][nt][hf * 2 + 1] + bz.y) * inv;
                *(float2*)&out[(size_t)(p0 + pp) * CZ + z] = make_float2(cx, cy);
            }
        }
    }
}

// ---------------------------------------------------------------------------
extern "C" void kernel_launch(void* const* d_in, const int* in_sizes, int n_in,
                              void* d_out, int out_size)
{
    const float* m     = (const float*)d_in[0];
    const float* mask  = (const float*)d_in[1];
    const float* lnw   = (const float*)d_in[2];
    const float* lnb   = (const float*)d_in[3];
    const float* w1    = (const float*)d_in[4];
    const float* b1    = (const float*)d_in[5];
    const float* w2    = (const float*)d_in[6];
    const float* b2    = (const float*)d_in[7];
    const float* w_out = (const float*)d_in[8];
    const float* b_out = (const float*)d_in[9];
    float* out = (float*)d_out;

    static int attr_done = 0;
    if (!attr_done) {
        cudaFuncSetAttribute(k_proj_fused,
            cudaFuncAttributeMaxDynamicSharedMemorySize, SMEM_P);
        cudaFuncSetAttribute(k_gemm1_mma,
            cudaFuncAttributeMaxDynamicSharedMemorySize, SMEM_G1);
        cudaFuncSetAttribute(k_gemm2_mma,
            cudaFuncAttributeMaxDynamicSharedMemorySize, SMEM_G2);
        attr_done = 1;
    }

    k_wprep<<<dim3(32, 4), dim3(32, 32)>>>(w_out);
    k_w12prep<<<64, 256>>>(w1, w2);
    k_proj_fused<<<256, 256, SMEM_P>>>(m, mask, lnw, lnb, b1, b2);
    k_gemm1_mma<<<dim3(64, 64), 256, SMEM_G1>>>();
    k_gemm2_mma<<<512, 512, SMEM_G2>>>(mask, b_out, out);
}